// round 14
// baseline (speedup 1.0000x reference)
#include <cuda_runtime.h>
#include <cstdint>

// ---------------------------------------------------------------------------
// Problem constants
// ---------------------------------------------------------------------------
#define BB 4
#define HH 224
#define WW 224
#define HW (HH * WW)                 // 50176
#define NPLANE 128                   // B*C
#define NTOT ((size_t)NPLANE * HW)   // 6,422,528 floats

// vertical scan pipeline (proven path)
#define ST 4
#define NS 3
#define NGRP (HH / ST)               // 56

// horizontal scan slab pipeline
#define STH 32                       // steps per stage (128B per row per array)
#define NSH 2
#define HGRP (WW / STH)              // 7
#define HARR (224 * STH * 4)         // bytes per array per stage = 28672
#define HSTAGEB (4 * HARR)           // 114688
#define HSMEM (NSH * HSTAGEB + 2 * 226 * 4)  // 231184

// Scratch (no cudaMalloc allowed)
__device__ __align__(256) float g_x[NTOT];
__device__ __align__(256) float g_dir[4 * NTOT];  // ALL native layout now

// ---------------------------------------------------------------------------
// cp.async helpers
// ---------------------------------------------------------------------------
__device__ __forceinline__ uint32_t s2u(const void* p) {
    return (uint32_t)__cvta_generic_to_shared(p);
}
__device__ __forceinline__ void cpa16(uint32_t dst, const float* src) {
    asm volatile("cp.async.cg.shared.global [%0], [%1], 16;" ::"r"(dst),
                 "l"(src));
}
__device__ __forceinline__ void cpa16p(float* dst, const float* src) {
    cpa16(s2u(dst), src);
}
__device__ __forceinline__ void cpa_commit() {
    asm volatile("cp.async.commit_group;");
}
__device__ __forceinline__ void cpa_wait2() {
    asm volatile("cp.async.wait_group 2;");
}
__device__ __forceinline__ void cpa_wait1() {
    asm volatile("cp.async.wait_group 1;");
}

// ---------------------------------------------------------------------------
// K0: conv2d 3x3 same, 2 -> 32, writes g_x
// ---------------------------------------------------------------------------
__global__ void conv_in_kernel(const float* __restrict__ y,
                               const float* __restrict__ w3) {
    __shared__ float ws[576];
    for (int i = threadIdx.x; i < 576; i += blockDim.x) ws[i] = w3[i];
    __syncthreads();

    int idx = blockIdx.x * blockDim.x + threadIdx.x;
    if (idx >= BB * HW) return;
    int b = idx / HW, pix = idx - b * HW;
    int py = pix / WW, px = pix - py * WW;

    float in[2][3][3];
#pragma unroll
    for (int ic = 0; ic < 2; ic++)
#pragma unroll
        for (int ky = 0; ky < 3; ky++)
#pragma unroll
            for (int kx = 0; kx < 3; kx++) {
                int yy = py + ky - 1, xx = px + kx - 1;
                bool v = ((unsigned)yy < HH) && ((unsigned)xx < WW);
                in[ic][ky][kx] =
                    v ? __ldg(y + ((size_t)(b * 2 + ic)) * HW + yy * WW + xx)
                      : 0.0f;
            }

    for (int oc = 0; oc < 32; oc++) {
        float a = 0.0f;
#pragma unroll
        for (int ic = 0; ic < 2; ic++)
#pragma unroll
            for (int k = 0; k < 9; k++)
                a += in[ic][k / 3][k % 3] * ws[(oc * 2 + ic) * 9 + k];
        g_x[((size_t)(b * 32 + oc)) * HW + pix] = a;
    }
}

// ---------------------------------------------------------------------------
// Vertical scan (d1 rl = H reverse, d2 du = H forward).
// ---------------------------------------------------------------------------
template <bool REV>
__device__ void scan_v_body(const float* __restrict__ g1,
                            const float* __restrict__ g2,
                            const float* __restrict__ g3,
                            const float* __restrict__ xp,
                            float* __restrict__ yp,
                            float (*sbuf)[4][ST * 224], float (*hbuf)[226],
                            int s) {
    const float* arr[4] = {g1, g2, g3, xp};
    const int jf = s / 56, qf = s - jf * 56;

    auto fill = [&](int st, int tg) {
        int row = REV ? 223 - (4 * tg + jf) : 4 * tg + jf;
#pragma unroll
        for (int a = 0; a < 4; a++)
            cpa16p(&sbuf[st][a][jf * 224 + qf * 4],
                   arr[a] + (size_t)row * WW + qf * 4);
        cpa_commit();
    };

    fill(0, 0);
    fill(1, 1);
    fill(2, 2);

    int cur = 0;
    float hown = 0.0f;

    for (int tg = 0; tg < NGRP; tg++) {
        int st = tg % NS;
        cpa_wait2();
        __syncthreads();

        float a1[ST], a2[ST], a3[ST], cx[ST];
#pragma unroll
        for (int j = 0; j < ST; j++) {
            float G1 = sbuf[st][0][j * 224 + s];
            float G2 = sbuf[st][1][j * 224 + s];
            float G3 = sbuf[st][2][j * 224 + s];
            float X = sbuf[st][3][j * 224 + s];
            float inv = __fdividef(
                1.0f, fmaxf(fabsf(G1) + fabsf(G2) + fabsf(G3), 1.0f));
            a1[j] = G1 * inv;
            a2[j] = G2 * inv;
            a3[j] = G3 * inv;
            cx[j] = (1.0f - a1[j] - a2[j] - a3[j]) * X;
        }

#pragma unroll
        for (int j = 0; j < ST; j++) {
            float hl = hbuf[cur][s];
            float hr = hbuf[cur][s + 2];
            float hn =
                fmaf(a1[j], hl, fmaf(a2[j], hown, fmaf(a3[j], hr, cx[j])));
            hbuf[cur ^ 1][s + 1] = hn;
            hown = hn;
            cur ^= 1;
            __syncthreads();
            int row = REV ? 223 - (4 * tg + j) : 4 * tg + j;
            yp[(size_t)row * WW + s] = hn;  // coalesced
        }

        int nt = tg + NS;
        if (nt < NGRP) fill(st, nt);
        else cpa_commit();
    }
}

__global__ void __launch_bounds__(224) scan_v_kernel(
    const float* __restrict__ gates) {
    __shared__ float sbuf[NS][4][ST * 224];
    __shared__ float hbuf[2][226];

    int s = threadIdx.x;
    int plane = blockIdx.x;
    int d = blockIdx.y + 1;  // 1 or 2
    int b = plane >> 5, c = plane & 31;
    int grp0 = (d == 1) ? 3 : 6;

    const float* g1 = gates + ((size_t)(b * 384 + (grp0 + 0) * 32 + c)) * HW;
    const float* g2 = gates + ((size_t)(b * 384 + (grp0 + 1) * 32 + c)) * HW;
    const float* g3 = gates + ((size_t)(b * 384 + (grp0 + 2) * 32 + c)) * HW;
    const float* xp = g_x + (size_t)plane * HW;
    float* yp = g_dir + (size_t)d * NTOT + (size_t)plane * HW;

    hbuf[0][s + 1] = 0.0f;
    if (s < 2) { hbuf[0][s * 225] = 0.0f; hbuf[1][s * 225] = 0.0f; }
    __syncthreads();

    if (d == 1) scan_v_body<true>(g1, g2, g3, xp, yp, sbuf, hbuf, s);
    else        scan_v_body<false>(g1, g2, g3, xp, yp, sbuf, hbuf, s);
}

// ---------------------------------------------------------------------------
// Horizontal scan on native layout (d0 lr = W fwd, d3 ud = W rev).
// Slab stage: 4 arrays x 224 rows x 32 cols. After a chunk is consumed, the
// chain's 4 outputs are stored back IN PLACE into the array-0 chunk slot
// (STS.128, same swizzle -> conflict-free). After the 8 chunk-groups, the
// 224x32 output tile is drained to global as 128B row segments (coalesced,
// NATIVE layout). No transposed buffers anywhere.
// ---------------------------------------------------------------------------
template <bool REV>
__device__ void scan_h_body(const float* __restrict__ g1,
                            const float* __restrict__ g2,
                            const float* __restrict__ g3,
                            const float* __restrict__ xp,
                            float* __restrict__ yp, char* slab,
                            float (*hbuf)[226], int s) {
    const float* arr[4] = {g1, g2, g3, xp};

    auto fill = [&](int st, int tg) {
        uint32_t sb = s2u(slab) + (uint32_t)(st * HSTAGEB);
        int base = REV ? 192 - 32 * tg : 32 * tg;
#pragma unroll
        for (int i = 0; i < 32; i++) {
            int a = i >> 3;
            int r = (i & 7) * 224 + s;
            int row = r >> 3, ch = r & 7;
            cpa16(sb + (uint32_t)(a * HARR + row * 128 +
                                  ((ch ^ (row & 7)) << 4)),
                  arr[a] + (size_t)row * WW + base + ch * 4);
        }
        cpa_commit();
    };

    fill(0, 0);
    fill(1, 1);

    int cur = 0;
    float hown = 0.0f;

    for (int tg = 0; tg < HGRP; tg++) {
        int st = tg & 1;
        cpa_wait1();
        __syncthreads();
        char* sp = slab + st * HSTAGEB;
        int base = REV ? 192 - 32 * tg : 32 * tg;

#pragma unroll
        for (int m = 0; m < 8; m++) {
            int cm = REV ? 7 - m : m;
            uint32_t coff = (uint32_t)(s * 128 + ((cm ^ (s & 7)) << 4));
            float4 q[4];
#pragma unroll
            for (int a = 0; a < 4; a++)
                q[a] = *(const float4*)(sp + a * HARR + coff);

            float a1[4], a2[4], a3[4], cx[4];
#pragma unroll
            for (int j = 0; j < 4; j++) {
                int cc = REV ? 3 - j : j;
                float G1 = ((const float*)&q[0])[cc];
                float G2 = ((const float*)&q[1])[cc];
                float G3 = ((const float*)&q[2])[cc];
                float X = ((const float*)&q[3])[cc];
                float inv = __fdividef(
                    1.0f, fmaxf(fabsf(G1) + fabsf(G2) + fabsf(G3), 1.0f));
                a1[j] = G1 * inv;
                a2[j] = G2 * inv;
                a3[j] = G3 * inv;
                cx[j] = (1.0f - a1[j] - a2[j] - a3[j]) * X;
            }

            float hv[4];
#pragma unroll
            for (int j = 0; j < 4; j++) {
                float hl = hbuf[cur][s];
                float hr = hbuf[cur][s + 2];
                float hn = fmaf(a1[j], hl,
                                fmaf(a2[j], hown, fmaf(a3[j], hr, cx[j])));
                hbuf[cur ^ 1][s + 1] = hn;
                hown = hn;
                hv[j] = hn;
                cur ^= 1;
                __syncthreads();
            }
            // In-place output into array-0 chunk slot (own row only).
            float4 ov;
            if (REV) { ov.x = hv[3]; ov.y = hv[2]; ov.z = hv[1]; ov.w = hv[0]; }
            else     { ov.x = hv[0]; ov.y = hv[1]; ov.z = hv[2]; ov.w = hv[3]; }
            *(float4*)(sp + coff) = ov;
        }

        __syncthreads();  // all output chunks written
        // Drain 224x32 tile to global, native layout, coalesced.
#pragma unroll
        for (int it = 0; it < 8; it++) {
            int i = s + 224 * it;
            int row = i >> 3, ch = i & 7;
            float4 v = *(const float4*)(sp + row * 128 +
                                        ((ch ^ (row & 7)) << 4));
            *(float4*)(yp + (size_t)row * WW + base + ch * 4) = v;
        }
        __syncthreads();  // drain reads done before refill overwrites

        if (tg + 2 < HGRP) fill(st, tg + 2);
        else cpa_commit();
    }
}

__global__ void __launch_bounds__(224) scan_h_kernel(
    const float* __restrict__ gates) {
    extern __shared__ __align__(128) char hsm[];
    float(*hbuf)[226] = (float(*)[226])(hsm + NSH * HSTAGEB);

    int s = threadIdx.x;
    int plane = blockIdx.x;
    int dh = blockIdx.y;  // 0 -> d0 (fwd), 1 -> d3 (rev)
    int b = plane >> 5, c = plane & 31;
    int grp0 = dh ? 9 : 0;

    const float* g1 = gates + ((size_t)(b * 384 + (grp0 + 0) * 32 + c)) * HW;
    const float* g2 = gates + ((size_t)(b * 384 + (grp0 + 1) * 32 + c)) * HW;
    const float* g3 = gates + ((size_t)(b * 384 + (grp0 + 2) * 32 + c)) * HW;
    const float* xp = g_x + (size_t)plane * HW;
    float* yp = g_dir + (size_t)(dh ? 3 : 0) * NTOT + (size_t)plane * HW;

    hbuf[0][s + 1] = 0.0f;
    if (s < 2) { hbuf[0][s * 225] = 0.0f; hbuf[1][s * 225] = 0.0f; }
    __syncthreads();

    if (dh) scan_h_body<true>(g1, g2, g3, xp, yp, hsm, hbuf, s);
    else    scan_h_body<false>(g1, g2, g3, xp, yp, hsm, hbuf, s);
}

// ---------------------------------------------------------------------------
// Combine (pass 1): g_x = elementwise max over 4 native buffers (float4).
// ---------------------------------------------------------------------------
__global__ void combine_kernel() {
    const size_t n4 = NTOT / 4;
    const float4* p0 = (const float4*)g_dir;
    const float4* p1 = (const float4*)(g_dir + NTOT);
    const float4* p2 = (const float4*)(g_dir + 2 * NTOT);
    const float4* p3 = (const float4*)(g_dir + 3 * NTOT);
    float4* o = (float4*)g_x;
    for (size_t i = blockIdx.x * (size_t)blockDim.x + threadIdx.x; i < n4;
         i += (size_t)gridDim.x * blockDim.x) {
        float4 a = __ldg(p0 + i), b = __ldg(p1 + i);
        float4 c = __ldg(p2 + i), d = __ldg(p3 + i);
        float4 r;
        r.x = fmaxf(fmaxf(a.x, b.x), fmaxf(c.x, d.x));
        r.y = fmaxf(fmaxf(a.y, b.y), fmaxf(c.y, d.y));
        r.z = fmaxf(fmaxf(a.z, b.z), fmaxf(c.z, d.z));
        r.w = fmaxf(fmaxf(a.w, b.w), fmaxf(c.w, d.w));
        o[i] = r;
    }
}

// ---------------------------------------------------------------------------
// FUSED pass-2 epilogue: combine(max of 4 dirs) + conv2d 3x3 (32->2) +
// log_softmax. Grid (7,7,B); block 32x8; each block: 32x32 output tile.
// Loops channels; per channel loads 34x34 halo'd combined tile into smem.
// The combined tensor is never materialized in global memory.
// ---------------------------------------------------------------------------
__global__ void __launch_bounds__(256) fused_out_kernel(
    const float* __restrict__ w4, float* __restrict__ out) {
    __shared__ float ws[576];
    __shared__ float tile[34][35];

    int tid = threadIdx.y * 32 + threadIdx.x;
    for (int i = tid; i < 576; i += 256) ws[i] = w4[i];

    int b = blockIdx.z;
    int x0 = blockIdx.x * 32, y0 = blockIdx.y * 32;
    int tx = threadIdx.x, ty = threadIdx.y;

    float acc0[4] = {0.f, 0.f, 0.f, 0.f};
    float acc1[4] = {0.f, 0.f, 0.f, 0.f};

    for (int c = 0; c < 32; c++) {
        size_t po = ((size_t)(b * 32 + c)) * HW;
        __syncthreads();  // previous channel's reads done (and ws on c=0)
        for (int idx = tid; idx < 34 * 34; idx += 256) {
            int ry = idx / 34, rx = idx - ry * 34;
            int gy = y0 + ry - 1, gx = x0 + rx - 1;
            float v = 0.0f;
            if ((unsigned)gy < HH && (unsigned)gx < WW) {
                size_t o = po + (size_t)gy * WW + gx;
                float v0 = __ldg(g_dir + o);
                float v1 = __ldg(g_dir + NTOT + o);
                float v2 = __ldg(g_dir + 2 * NTOT + o);
                float v3 = __ldg(g_dir + 3 * NTOT + o);
                v = fmaxf(fmaxf(v0, v1), fmaxf(v2, v3));
            }
            tile[ry][rx] = v;
        }
        __syncthreads();

#pragma unroll
        for (int k = 0; k < 4; k++) {
            int r = ty + 8 * k;
#pragma unroll
            for (int dy = 0; dy < 3; dy++)
#pragma unroll
                for (int dx = 0; dx < 3; dx++) {
                    float v = tile[r + dy][tx + dx];
                    int wi = c * 9 + dy * 3 + dx;
                    acc0[k] = fmaf(v, ws[wi], acc0[k]);
                    acc1[k] = fmaf(v, ws[288 + wi], acc1[k]);
                }
        }
    }

#pragma unroll
    for (int k = 0; k < 4; k++) {
        int r = ty + 8 * k;
        int pix = (y0 + r) * WW + x0 + tx;
        float a0 = acc0[k], a1 = acc1[k];
        float mx = fmaxf(a0, a1);
        float l = mx + logf(expf(a0 - mx) + expf(a1 - mx));
        out[(size_t)(b * 2) * HW + pix] = a0 - l;
        out[(size_t)(b * 2 + 1) * HW + pix] = a1 - l;
    }
}

// ---------------------------------------------------------------------------
// Launch: conv_in -> scan_v+scan_h -> combine -> scan_v+scan_h -> fused_out
// ---------------------------------------------------------------------------
extern "C" void kernel_launch(void* const* d_in, const int* in_sizes, int n_in,
                              void* d_out, int out_size) {
    const float* gates = (const float*)d_in[0];
    const float* y     = (const float*)d_in[1];
    const float* w3    = (const float*)d_in[2];
    const float* w4    = (const float*)d_in[3];
    float* out = (float*)d_out;

    cudaFuncSetAttribute(scan_h_kernel,
                         cudaFuncAttributeMaxDynamicSharedMemorySize, HSMEM);

    int pxblocks = (BB * HW + 255) / 256;
    dim3 sg(NPLANE, 2);
    dim3 fb(32, 8);
    dim3 fg(7, 7, BB);

    conv_in_kernel<<<pxblocks, 256>>>(y, w3);
    scan_v_kernel<<<sg, 224>>>(gates);
    scan_h_kernel<<<sg, 224, HSMEM>>>(gates);
    combine_kernel<<<2048, 256>>>();
    scan_v_kernel<<<sg, 224>>>(gates);
    scan_h_kernel<<<sg, 224, HSMEM>>>(gates);
    fused_out_kernel<<<fg, fb>>>(w4, out);
}